// round 11
// baseline (speedup 1.0000x reference)
#include <cuda_runtime.h>
#include <math.h>

#define BB 16
#define HH 384
#define WW 384
#define NPIX (BB * HH * WW)
#define TILE 8                  // output rows per block
#define NRR (TILE + 6)          // mask rows incl +-3 halo = 14
#define WPR 14                  // words per mask row: 1 pad + 12 + 1 pad
#define NTILES (HH / TILE)      // 48
#define NBLK (BB * NTILES)      // 768
#define TABBIG 589824           // 768^2 = clipped-BIG^2 (matches reference)

__device__ float g_partial[NBLK];
__device__ int g_count = 0;     // reset by finisher each run

// ---------------------------------------------------------------------------
// Exact pruned brute-force EDT fallback (P ~ 2^-45 per pixel on this data).
// ub is a valid upper bound; returns exact min(ub, true d^2), reproducing the
// reference's BIG-clip when no foreground exists.
// ---------------------------------------------------------------------------
__device__ __noinline__ int edt_fallback(const int* __restrict__ timg,
                                         int i, int j, int ub) {
    int best = ub;
    for (int r = 0; r < HH; ++r) {
        if (r * r >= best) break;
        #pragma unroll 1
        for (int s = 0; s < 2; ++s) {
            if (s == 1 && r == 0) continue;
            const int row = s ? i + r : i - r;
            if (row < 0 || row >= HH) continue;
            for (int dd = 0; ; ++dd) {
                const int d2 = r * r + dd * dd;
                if (d2 >= best) break;
                int hit = 0;
                if (j - dd >= 0 && timg[row * WW + j - dd]) hit = 1;
                if (j + dd < WW && timg[row * WW + j + dd]) hit = 1;
                if (hit) { best = d2; break; }
            }
        }
    }
    return best;
}

// ---------------------------------------------------------------------------
// Fused single-pass kernel (R7 structure + early logits prefetch).
// Block = 8 rows x 384 cols of one image.
// Logits: both float4 loads issued at the TOP of the kernel so their DRAM
//         latency is hidden under the entire phase A (they're consumed only
//         in phase B; phase A's live register set is small so the peak
//         pressure — in phase B, where they were live anyway — is unchanged).
// Phase A: fg bitmasks for 14 rows (ballot), zero-padded words at both ends;
//          halo rows clamped at image edges (exact: clamped row already
//          counted at its true smaller offset, r^2+g^2 only overshoots).
// Phase B: per pixel, 32-bit window per row via funnelshift; fold +-r rows by
//          OR; 4 smem-table lookups give min dd^2; best = min_k(k^2 + tab).
//          best < 16 is provably exact; else exact fallback. Fused with
//          sigmoid loss (|sig(x)-t| = 1/(1+exp(t?x:-x)), t = center bit).
// Tail: block reduction -> partial; last finished block sums all partials
//       in a fixed deterministic tree and writes out[0].
// ---------------------------------------------------------------------------
__global__ __launch_bounds__(WW)
void fused_kernel(const float* __restrict__ logits,
                  const int* __restrict__ targets,
                  float* __restrict__ out) {
    __shared__ unsigned pm[NRR][WPR];
    __shared__ int tabs[128];
    __shared__ float sqtab[32];
    __shared__ float warp_sums[WW / 32];
    __shared__ int is_last;

    const int tid = threadIdx.x;                // 0..383
    const int bid = blockIdx.x;
    const int b = bid / NTILES;
    const int row0 = (bid % NTILES) * TILE;

    const int* timg = targets + (size_t)b * HH * WW;
    const float* limg = logits + (size_t)b * HH * WW;

    // Phase-B geometry (needed for the prefetch addresses)
    const int q = tid % 96;
    const int kl = (tid / 96) * 2;              // 0,2,4,6
    const int j = q * 4;
    const int i0 = row0 + kl;

    // EARLY logits prefetch: latency hidden under all of phase A
    const float4 lgA = *(const float4*)(limg + i0 * WW + j);
    const float4 lgB = *(const float4*)(limg + (i0 + 1) * WW + j);

    // Tables + pad words
    if (tid < 128) {
        const unsigned w = (unsigned)tid;
        tabs[tid] = (w & 0x08u) ? 0 :
                    (w & 0x14u) ? 1 :
                    (w & 0x22u) ? 4 :
                    (w & 0x41u) ? 9 : TABBIG;
        if (tid < 32) sqtab[tid] = sqrtf((float)tid);
        if (tid < NRR) { pm[tid][0] = 0u; pm[tid][WPR - 1] = 0u; }
    }

    // Phase A: bitmasks (rows clamped into image)
    const int lane = tid & 31;
    #pragma unroll
    for (int rr = 0; rr < NRR; ++rr) {
        const int row = min(max(row0 - 3 + rr, 0), HH - 1);
        const int fg = timg[row * WW + tid] != 0;
        const unsigned m = __ballot_sync(0xFFFFFFFFu, fg);
        if (lane == 0) pm[rr][1 + (tid >> 5)] = m;
    }
    __syncthreads();

    // Phase B: thread -> column quad q (4 cols) x 2 adjacent rows
    const int word = (j + 29) >> 5;             // bitpos of col j-3, padded
    const int sh = (j + 29) & 31;

    unsigned win[8];                            // mask rows kl .. kl+7
    #pragma unroll
    for (int w = 0; w < 8; ++w) {
        const unsigned* rp = pm[kl + w];
        win[w] = __funnelshift_r(rp[word], rp[word + 1], sh);
    }

    float val = 0.0f;
    #pragma unroll
    for (int m = 0; m < 2; ++m) {
        const int ci = 3 + m;                   // center within win[]
        const int i = i0 + m;
        const unsigned A0 = win[ci];
        const unsigned A1 = win[ci - 1] | win[ci + 1];
        const unsigned A2 = win[ci - 2] | win[ci + 2];
        const unsigned A3 = win[ci - 3] | win[ci + 3];

        const float4 lg = m ? lgB : lgA;
        const float xs[4] = {lg.x, lg.y, lg.z, lg.w};

        #pragma unroll
        for (int c = 0; c < 4; ++c) {
            const int b0 = tabs[(A0 >> c) & 127u];
            const int b1 = tabs[(A1 >> c) & 127u] + 1;
            const int b2 = tabs[(A2 >> c) & 127u] + 4;
            const int b3 = tabs[(A3 >> c) & 127u] + 9;
            int best = min(min(b0, b1), min(b2, b3));
            if (best >= 16) best = edt_fallback(timg, i, j + c, best);

            const int tbit = (A0 >> (c + 3)) & 1u;
            const float e = __expf(tbit ? xs[c] : -xs[c]);
            const float sq = (best < 32) ? sqtab[best] : sqrtf((float)best);
            val += __fdividef(sq, 1.0f + e);
        }
    }

    // Block reduction
    #pragma unroll
    for (int off = 16; off > 0; off >>= 1)
        val += __shfl_xor_sync(0xFFFFFFFFu, val, off);
    if (lane == 0) warp_sums[tid >> 5] = val;
    __syncthreads();
    if (tid < 32) {
        float s = (tid < WW / 32) ? warp_sums[tid] : 0.0f;
        #pragma unroll
        for (int off = 16; off > 0; off >>= 1)
            s += __shfl_xor_sync(0xFFFFFFFFu, s, off);
        if (tid == 0) {
            g_partial[bid] = s;
            __threadfence();
            const int done = atomicAdd(&g_count, 1);
            is_last = (done == NBLK - 1);
        }
    }
    __syncthreads();

    // Last block: deterministic final sum of all 768 partials
    if (is_last) {
        __threadfence();
        float v = g_partial[tid] + g_partial[tid + WW];
        #pragma unroll
        for (int off = 16; off > 0; off >>= 1)
            v += __shfl_xor_sync(0xFFFFFFFFu, v, off);
        if (lane == 0) warp_sums[tid >> 5] = v;
        __syncthreads();
        if (tid < 32) {
            float s = (tid < WW / 32) ? warp_sums[tid] : 0.0f;
            #pragma unroll
            for (int off = 16; off > 0; off >>= 1)
                s += __shfl_xor_sync(0xFFFFFFFFu, s, off);
            if (tid == 0) {
                out[0] = s * (1.0f / (float)NPIX);
                g_count = 0;                    // reset for next graph replay
            }
        }
    }
}

extern "C" void kernel_launch(void* const* d_in, const int* in_sizes, int n_in,
                              void* d_out, int out_size) {
    const float* logits = (const float*)d_in[0];
    const int* targets = (const int*)d_in[1];
    float* out = (float*)d_out;

    (void)in_sizes; (void)n_in; (void)out_size;

    fused_kernel<<<NBLK, WW>>>(logits, targets, out);
}

// round 12
// speedup vs baseline: 1.1830x; 1.1830x over previous
#include <cuda_runtime.h>
#include <math.h>

#define BB 16
#define HH 384
#define WW 384
#define NPIX (BB * HH * WW)
#define TILE 8                  // output rows per block
#define NRR (TILE + 6)          // mask rows incl +-3 halo = 14
#define WPR 14                  // words per mask row: 1 pad + 12 + 1 pad
#define NTILES (HH / TILE)      // 48
#define NBLK (BB * NTILES)      // 768
#define BIGB 200                // window-miss marker (>=16 -> exact fallback)

__device__ float g_partial[NBLK];
__device__ int g_count = 0;     // reset by finisher each run

// ---------------------------------------------------------------------------
// Exact pruned brute-force EDT fallback (P ~ 2^-45 per pixel on this data).
// ub is a valid upper bound; returns exact min(ub, true d^2); reproduces the
// reference's BIG-clip (768^2) when no foreground exists.
// ---------------------------------------------------------------------------
__device__ __noinline__ int edt_fallback(const int* __restrict__ timg,
                                         int i, int j, int ub) {
    int best = 589824;          // 768^2 = clipped BIG^2 (reference semantics)
    if (ub < best) best = ub;
    for (int r = 0; r < HH; ++r) {
        if (r * r >= best) break;
        #pragma unroll 1
        for (int s = 0; s < 2; ++s) {
            if (s == 1 && r == 0) continue;
            const int row = s ? i + r : i - r;
            if (row < 0 || row >= HH) continue;
            for (int dd = 0; ; ++dd) {
                const int d2 = r * r + dd * dd;
                if (d2 >= best) break;
                int hit = 0;
                if (j - dd >= 0 && timg[row * WW + j - dd]) hit = 1;
                if (j + dd < WW && timg[row * WW + j + dd]) hit = 1;
                if (hit) { best = d2; break; }
            }
        }
    }
    return best;
}

// min horizontal dd^2 within +-3 for 7-bit window w (center = bit 3)
__device__ __forceinline__ int mind7(unsigned w) {
    return (w & 0x08u) ? 0 :
           (w & 0x14u) ? 1 :
           (w & 0x22u) ? 4 :
           (w & 0x41u) ? 9 : BIGB;
}

// ---------------------------------------------------------------------------
// Fused single-pass kernel (R7 structure; pair-packed phase-B tables).
// Phase A: fg bitmasks for 14 rows (ballot), pad words zeroed; halo rows
//          clamped at image edges (exact: clamped row already counted at its
//          true smaller offset; r^2+g^2 only overshoots).
// Phase B: per pixel-PAIR, one u32 table entry per vertical level r gives
//          (r^2 + min dd^2) for two adjacent columns (lo/hi u16); accumulate
//          with __vminu2. best < 16 provably exact; else exact fallback.
//          Fused sigmoid loss: |sig(x)-t| = 1/(1+exp(t?x:-x)), t = center
//          bit. sqrt via MUFU (sqrt.approx) - no sqtab LDS.
// Tail: block reduction -> partial; last finished block sums all partials
//       deterministically and writes out[0].
// ---------------------------------------------------------------------------
__global__ __launch_bounds__(WW)
void fused_kernel(const float* __restrict__ logits,
                  const int* __restrict__ targets,
                  float* __restrict__ out) {
    __shared__ unsigned pm[NRR][WPR];
    __shared__ unsigned tp[4][256];             // [level r][8-bit window slice]
    __shared__ float warp_sums[WW / 32];
    __shared__ int is_last;

    const int tid = threadIdx.x;                // 0..383
    const int lane = tid & 31;
    const int bid = blockIdx.x;
    const int b = bid / NTILES;
    const int row0 = (bid % NTILES) * TILE;

    const int* timg = targets + (size_t)b * HH * WW;
    const float* limg = logits + (size_t)b * HH * WW;

    // Table init: entry = (r^2 + mind7(lo-window)) | (r^2 + mind7(hi)) << 16
    #pragma unroll
    for (int t = tid; t < 1024; t += WW) {
        const int r = t >> 8;
        const unsigned byte = (unsigned)(t & 255);
        const int off = r * r;
        const unsigned lo = (unsigned)(mind7(byte & 127u) + off);
        const unsigned hi = (unsigned)(mind7((byte >> 1) & 127u) + off);
        tp[r][byte] = lo | (hi << 16);
    }
    if (tid < NRR) { pm[tid][0] = 0u; pm[tid][WPR - 1] = 0u; }

    // Phase A: bitmasks (rows clamped into image)
    #pragma unroll
    for (int rr = 0; rr < NRR; ++rr) {
        const int row = min(max(row0 - 3 + rr, 0), HH - 1);
        const int fg = timg[row * WW + tid] != 0;
        const unsigned m = __ballot_sync(0xFFFFFFFFu, fg);
        if (lane == 0) pm[rr][1 + (tid >> 5)] = m;
    }
    __syncthreads();

    // Phase B: thread -> column quad q (4 cols) x 2 adjacent rows
    const int q = tid % 96;
    const int kl = (tid / 96) * 2;              // 0,2,4,6
    const int j = q * 4;
    const int word = (j + 29) >> 5;             // bitpos of col j-3, padded
    const int sh = (j + 29) & 31;

    unsigned win[8];                            // mask rows kl .. kl+7
    #pragma unroll
    for (int w = 0; w < 8; ++w) {
        const unsigned* rp = pm[kl + w];
        win[w] = __funnelshift_r(rp[word], rp[word + 1], sh);
    }

    float val = 0.0f;
    #pragma unroll
    for (int m = 0; m < 2; ++m) {
        const int ci = 3 + m;                   // center within win[]
        const int i = row0 + kl + m;
        const unsigned A0 = win[ci];
        const unsigned A1 = win[ci - 1] | win[ci + 1];
        const unsigned A2 = win[ci - 2] | win[ci + 2];
        const unsigned A3 = win[ci - 3] | win[ci + 3];

        // Pair (cols 0,1): window byte = bits 0..7; pair (2,3): bits 2..9
        unsigned bp0 = tp[0][A0 & 255u];
        unsigned bp1 = tp[0][(A0 >> 2) & 255u];
        bp0 = __vminu2(bp0, tp[1][A1 & 255u]);
        bp1 = __vminu2(bp1, tp[1][(A1 >> 2) & 255u]);
        bp0 = __vminu2(bp0, tp[2][A2 & 255u]);
        bp1 = __vminu2(bp1, tp[2][(A2 >> 2) & 255u]);
        bp0 = __vminu2(bp0, tp[3][A3 & 255u]);
        bp1 = __vminu2(bp1, tp[3][(A3 >> 2) & 255u]);

        int bests[4];
        bests[0] = (int)(bp0 & 0xFFFFu);
        bests[1] = (int)(bp0 >> 16);
        bests[2] = (int)(bp1 & 0xFFFFu);
        bests[3] = (int)(bp1 >> 16);

        const float4 lg = *(const float4*)(limg + i * WW + j);
        const float xs[4] = {lg.x, lg.y, lg.z, lg.w};

        #pragma unroll
        for (int c = 0; c < 4; ++c) {
            int best = bests[c];
            if (best >= 16) best = edt_fallback(timg, i, j + c, best);

            const int tbit = (A0 >> (c + 3)) & 1u;
            const float e = __expf(tbit ? xs[c] : -xs[c]);
            float sq;
            asm("sqrt.approx.f32 %0, %1;" : "=f"(sq) : "f"((float)best));
            val += __fdividef(sq, 1.0f + e);
        }
    }

    // Block reduction
    #pragma unroll
    for (int off = 16; off > 0; off >>= 1)
        val += __shfl_xor_sync(0xFFFFFFFFu, val, off);
    if (lane == 0) warp_sums[tid >> 5] = val;
    __syncthreads();
    if (tid < 32) {
        float s = (tid < WW / 32) ? warp_sums[tid] : 0.0f;
        #pragma unroll
        for (int off = 16; off > 0; off >>= 1)
            s += __shfl_xor_sync(0xFFFFFFFFu, s, off);
        if (tid == 0) {
            g_partial[bid] = s;
            __threadfence();
            const int done = atomicAdd(&g_count, 1);
            is_last = (done == NBLK - 1);
        }
    }
    __syncthreads();

    // Last block: deterministic final sum of all 768 partials
    if (is_last) {
        __threadfence();
        float v = g_partial[tid] + g_partial[tid + WW];
        #pragma unroll
        for (int off = 16; off > 0; off >>= 1)
            v += __shfl_xor_sync(0xFFFFFFFFu, v, off);
        if (lane == 0) warp_sums[tid >> 5] = v;
        __syncthreads();
        if (tid < 32) {
            float s = (tid < WW / 32) ? warp_sums[tid] : 0.0f;
            #pragma unroll
            for (int off = 16; off > 0; off >>= 1)
                s += __shfl_xor_sync(0xFFFFFFFFu, s, off);
            if (tid == 0) {
                out[0] = s * (1.0f / (float)NPIX);
                g_count = 0;                    // reset for next graph replay
            }
        }
    }
}

extern "C" void kernel_launch(void* const* d_in, const int* in_sizes, int n_in,
                              void* d_out, int out_size) {
    const float* logits = (const float*)d_in[0];
    const int* targets = (const int*)d_in[1];
    float* out = (float*)d_out;

    (void)in_sizes; (void)n_in; (void)out_size;

    fused_kernel<<<NBLK, WW>>>(logits, targets, out);
}